// round 4
// baseline (speedup 1.0000x reference)
#include <cuda_runtime.h>
#include <cuda_bf16.h>

#define NMAX 50000
#define EMAX 800000
#define F 128
#define EFD 6

#define PREP_BLOCKS 592          // 4 CTAs/SM x 148 SMs, co-resident by launch_bounds
#define PREP_T 512

// ---------------- device scratch ----------------
__device__ int    g_is64;
__device__ int    g_counts[NMAX];
__device__ int    g_cursor[NMAX];
__device__ int    g_rowptr[NMAX + 1];
__device__ int    g_src[EMAX];
__device__ int    g_dst[EMAX];
__device__ int2   g_edges[EMAX];
__device__ int    g_blocksum[256];
__device__ int    g_blockoff[256];
__device__ int    g_bar[5];      // software grid barriers (zero-init first launch)

// ---------------- software grid barrier -------------------------------------
__device__ __forceinline__ void grid_barrier(int id) {
    __syncthreads();
    if (threadIdx.x == 0) {
        __threadfence();
        atomicAdd(&g_bar[id], 1);
        const volatile int* vb = g_bar;
        while (vb[id] < PREP_BLOCKS) { }
        __threadfence();
    }
    __syncthreads();
}

// ---------------- fused prep: zero+detect | hist | scan | scatter ------------
__global__ void __launch_bounds__(PREP_T, 4)
k_prep(const void* __restrict__ ei, int N, int E) {
    const int tid  = blockIdx.x * PREP_T + threadIdx.x;
    const int nth  = PREP_BLOCKS * PREP_T;
    const int lane = threadIdx.x & 31;
    const int T    = (N + 255) >> 8;

    // ---- P0: zero counts, detect index width, reset bar[4] from prior replay
    if (blockIdx.x == 0 && threadIdx.x == 0) {
        const long long* p = (const long long*)ei;
        int ok = 1;
        int lim = E < 128 ? E : 128;
        for (int j = 0; j < lim; j++) {
            long long v = p[j];
            if (v < 0 || v >= (long long)N) { ok = 0; break; }
        }
        g_is64 = ok;
        atomicExch(&g_bar[4], 0);
    }
    for (int i = tid; i < N; i += nth) g_counts[i] = 0;
    grid_barrier(0);

    // ---- P1: decode + histogram
    const int is64 = __ldcg(&g_is64);
    if (is64) {
        const longlong2* p = (const longlong2*)ei;
        for (int e = tid; e < E; e += nth) {
            longlong2 v = p[e];
            int s = (int)v.x, d = (int)v.y;
            g_src[e] = s; g_dst[e] = d;
            atomicAdd(&g_counts[d], 1);
        }
    } else {
        const int2* p = (const int2*)ei;
        for (int e = tid; e < E; e += nth) {
            int2 v = p[e];
            g_src[e] = v.x; g_dst[e] = v.y;
            atomicAdd(&g_counts[v.y], 1);
        }
    }
    grid_barrier(1);
    if (blockIdx.x == 0 && threadIdx.x == 0) atomicExch(&g_bar[0], 0);

    // ---- P2: per-tile (256) exclusive scan, one warp per tile
    {
        int gw = tid >> 5;
        int nw = nth >> 5;
        for (int t = gw; t < T; t += nw) {
            int base = t << 8;
            int v[8]; int s = 0;
            #pragma unroll
            for (int j = 0; j < 8; j++) {
                int idx = base + lane * 8 + j;
                int c = (idx < N) ? __ldcg(&g_counts[idx]) : 0;
                v[j] = s; s += c;
            }
            int x = s;
            #pragma unroll
            for (int o = 1; o < 32; o <<= 1) {
                int y = __shfl_up_sync(0xffffffffu, x, o);
                if (lane >= o) x += y;
            }
            int excl = x - s;
            #pragma unroll
            for (int j = 0; j < 8; j++) {
                int idx = base + lane * 8 + j;
                if (idx < N) g_rowptr[idx] = excl + v[j];
            }
            if (lane == 31) g_blocksum[t] = x;
        }
    }
    grid_barrier(2);
    if (blockIdx.x == 0 && threadIdx.x == 0) atomicExch(&g_bar[1], 0);

    // ---- P3: scan of tile sums (block 0, warp 0)
    if (blockIdx.x == 0 && threadIdx.x < 32) {
        int vals[7]; int s = 0;
        #pragma unroll
        for (int j = 0; j < 7; j++) {
            int idx = lane * 7 + j;
            int v = (idx < T) ? __ldcg(&g_blocksum[idx]) : 0;
            vals[j] = s; s += v;
        }
        int x = s;
        #pragma unroll
        for (int o = 1; o < 32; o <<= 1) {
            int y = __shfl_up_sync(0xffffffffu, x, o);
            if (lane >= o) x += y;
        }
        int excl = x - s;
        #pragma unroll
        for (int j = 0; j < 7; j++) {
            int idx = lane * 7 + j;
            if (idx < T) g_blockoff[idx] = excl + vals[j];
        }
        if (lane == 31) g_rowptr[N] = x;
    }
    grid_barrier(3);
    if (blockIdx.x == 0 && threadIdx.x == 0) atomicExch(&g_bar[2], 0);

    // ---- P4: add tile offsets, init cursor
    for (int i = tid; i < N; i += nth) {
        int r = __ldcg(&g_rowptr[i]) + __ldcg(&g_blockoff[i >> 8]);
        g_rowptr[i] = r;
        g_cursor[i] = r;
    }
    grid_barrier(4);
    if (blockIdx.x == 0 && threadIdx.x == 0) atomicExch(&g_bar[3], 0);

    // ---- P5: scatter edges into CSR slots (MLP=4)
    for (int e0 = tid * 4; e0 < E; e0 += nth * 4) {
        int d[4], s[4];
        #pragma unroll
        for (int j = 0; j < 4; j++) {
            int e = e0 + j;
            if (e < E) { d[j] = __ldcg(&g_dst[e]); s[j] = __ldcg(&g_src[e]); }
        }
        #pragma unroll
        for (int j = 0; j < 4; j++) {
            int e = e0 + j;
            if (e < E) {
                int p = atomicAdd(&g_cursor[d[j]], 1);
                g_edges[p] = make_int2(s[j], e);
            }
        }
    }
    // g_bar[4] reset at next replay's P0.
}

// ---------------- K45: fused gather-aggregate + GEMM + relu -----------------
#define K45_T 512
#define K45_W (K45_T / 32)       // 16 warps
#define RPW 8
#define K45_SMEM ((F*F + EFD*F + F) * 4 + K45_W * RPW * F * 4)

__global__ void __launch_bounds__(K45_T)
k45_fused(const float4* __restrict__ X4, const float* __restrict__ eF,
          const float* __restrict__ W, const float* __restrict__ b,
          const float* __restrict__ We, const float* __restrict__ be,
          float* __restrict__ out, int N) {
    extern __shared__ float smem[];
    float*  Ws   = smem;                 // 128*128
    float*  Wes  = Ws + F * F;           // 6*128
    float*  bsum = Wes + EFD * F;        // 128
    float4* xs   = (float4*)(bsum + F);  // 16 warps x 8 rows x 32 float4

    int tid = threadIdx.x;
    for (int i = tid; i < F * F; i += K45_T) Ws[i] = W[i];
    for (int i = tid; i < EFD * F; i += K45_T) Wes[i] = We[i];
    for (int i = tid; i < F; i += K45_T) bsum[i] = b[i] + be[i];
    __syncthreads();

    int warp = tid >> 5, lane = tid & 31;
    float4* xw4 = xs + warp * (RPW * 32);
    const float* xw = (const float*)xw4;

    int nGroups = (N + RPW - 1) / RPW;
    for (int g = blockIdx.x * K45_W + warp; g < nGroups;
         g += gridDim.x * K45_W) {
        int row0 = g * RPW;
        int nr = N - row0; if (nr > RPW) nr = RPW;

        float ae[RPW];
        int   degi[RPW];

        // ---- gather phase: sum X[src] for each of RPW nodes into smem slice
        #pragma unroll
        for (int r = 0; r < RPW; r++) {
            float4 acc = make_float4(0.f, 0.f, 0.f, 0.f);
            float a = 0.f;
            int deg = 0;
            if (r < nr) {
                int s0 = g_rowptr[row0 + r], s1 = g_rowptr[row0 + r + 1];
                deg = s1 - s0;
                for (int base = s0; base < s1; base += 32) {
                    int cnt = s1 - base; if (cnt > 32) cnt = 32;
                    int2 se = g_edges[base + (lane < cnt ? lane : 0)];
                    for (int j = 0; j < cnt; j += 8) {
                        #pragma unroll
                        for (int u = 0; u < 8; u++) {
                            if (j + u < cnt) {  // uniform across warp
                                int sj = __shfl_sync(0xffffffffu, se.x, j + u);
                                int ej = __shfl_sync(0xffffffffu, se.y, j + u);
                                float4 xv = X4[(long)sj * 32 + lane];
                                acc.x += xv.x; acc.y += xv.y;
                                acc.z += xv.z; acc.w += xv.w;
                                if (lane < EFD) a += eF[(long)ej * EFD + lane];
                            }
                        }
                    }
                }
            }
            xw4[r * 32 + lane] = acc;
            ae[r] = a;
            degi[r] = deg;
        }
        __syncwarp();

        // ---- GEMM phase: 8 rows x 128 cols, W from smem
        float4 acc[RPW];
        #pragma unroll
        for (int r = 0; r < RPW; r++) acc[r] = make_float4(0.f, 0.f, 0.f, 0.f);

        #pragma unroll 2
        for (int k = 0; k < F; k += 4) {
            float4 xv[RPW];
            #pragma unroll
            for (int r = 0; r < RPW; r++)
                xv[r] = *(const float4*)(xw + (r << 7) + k);   // smem broadcast
            #pragma unroll
            for (int kk = 0; kk < 4; kk++) {
                float4 w4 = ((const float4*)(Ws + ((k + kk) << 7)))[lane];
                #pragma unroll
                for (int r = 0; r < RPW; r++) {
                    float xk = (kk == 0) ? xv[r].x : (kk == 1) ? xv[r].y
                             : (kk == 2) ? xv[r].z : xv[r].w;
                    acc[r].x = fmaf(xk, w4.x, acc[r].x);
                    acc[r].y = fmaf(xk, w4.y, acc[r].y);
                    acc[r].z = fmaf(xk, w4.z, acc[r].z);
                    acc[r].w = fmaf(xk, w4.w, acc[r].w);
                }
            }
        }

        // ---- epilogue: deg*bias + edge GEMM + relu + store
        float4 b4 = ((const float4*)bsum)[lane];
        for (int r = 0; r < nr; r++) {
            int row = row0 + r;
            float deg = (float)degi[r];
            float4 o = acc[r];
            o.x = fmaf(deg, b4.x, o.x);
            o.y = fmaf(deg, b4.y, o.y);
            o.z = fmaf(deg, b4.z, o.z);
            o.w = fmaf(deg, b4.w, o.w);
            #pragma unroll
            for (int k = 0; k < EFD; k++) {
                float ek = __shfl_sync(0xffffffffu, ae[r], k);
                float4 w4 = ((const float4*)(Wes + (k << 7)))[lane];
                o.x = fmaf(ek, w4.x, o.x);
                o.y = fmaf(ek, w4.y, o.y);
                o.z = fmaf(ek, w4.z, o.z);
                o.w = fmaf(ek, w4.w, o.w);
            }
            o.x = fmaxf(o.x, 0.f); o.y = fmaxf(o.y, 0.f);
            o.z = fmaxf(o.z, 0.f); o.w = fmaxf(o.w, 0.f);
            ((float4*)out)[(long)row * 32 + lane] = o;
        }
        __syncwarp();
    }
}

// ---------------------------------------------------------------------------
extern "C" void kernel_launch(void* const* d_in, const int* in_sizes, int n_in,
                              void* d_out, int out_size) {
    const float* X  = (const float*)d_in[0];
    const void*  EI = d_in[1];
    const float* EF = (const float*)d_in[2];
    const float* W  = (const float*)d_in[3];
    const float* b  = (const float*)d_in[4];
    const float* We = (const float*)d_in[5];
    const float* be = (const float*)d_in[6];
    float* out = (float*)d_out;

    int N = in_sizes[0] / F;
    int E = in_sizes[2] / EFD;

    cudaFuncSetAttribute(k45_fused, cudaFuncAttributeMaxDynamicSharedMemorySize,
                         K45_SMEM);

    k_prep<<<PREP_BLOCKS, PREP_T>>>(EI, N, E);
    k45_fused<<<148, K45_T, K45_SMEM>>>((const float4*)X, EF, W, b, We, be,
                                        out, N);
}

// round 5
// speedup vs baseline: 1.3259x; 1.3259x over previous
#include <cuda_runtime.h>
#include <cuda_bf16.h>

#define NMAX 50000
#define EMAX 800000
#define F 128
#define EFD 6

#define PREP_BLOCKS 592
#define PREP_T 512

// ---------------- device scratch ----------------
__device__ int    g_is64;
__device__ int    g_counts[NMAX];
__device__ int    g_cursor[NMAX];
__device__ int    g_rowptr[NMAX + 1];
__device__ int    g_src[EMAX];
__device__ int    g_dst[EMAX];
__device__ int2   g_edges[EMAX];
__device__ int    g_blocksum[256];
__device__ int    g_blockoff[256];
__device__ int    g_bar[5];

// ---------------- software grid barrier -------------------------------------
__device__ __forceinline__ void grid_barrier(int id) {
    __syncthreads();
    if (threadIdx.x == 0) {
        __threadfence();
        atomicAdd(&g_bar[id], 1);
        const volatile int* vb = g_bar;
        while (vb[id] < PREP_BLOCKS) { }
        __threadfence();
    }
    __syncthreads();
}

// ---------------- fused prep: zero+detect | hist | scan | scatter ------------
__global__ void __launch_bounds__(PREP_T, 4)
k_prep(const void* __restrict__ ei, int N, int E) {
    const int tid  = blockIdx.x * PREP_T + threadIdx.x;
    const int nth  = PREP_BLOCKS * PREP_T;
    const int lane = threadIdx.x & 31;
    const int T    = (N + 255) >> 8;

    if (blockIdx.x == 0 && threadIdx.x == 0) {
        const long long* p = (const long long*)ei;
        int ok = 1;
        int lim = E < 128 ? E : 128;
        for (int j = 0; j < lim; j++) {
            long long v = p[j];
            if (v < 0 || v >= (long long)N) { ok = 0; break; }
        }
        g_is64 = ok;
        atomicExch(&g_bar[4], 0);
    }
    for (int i = tid; i < N; i += nth) g_counts[i] = 0;
    grid_barrier(0);

    const int is64 = __ldcg(&g_is64);
    if (is64) {
        const longlong2* p = (const longlong2*)ei;
        for (int e = tid; e < E; e += nth) {
            longlong2 v = p[e];
            int s = (int)v.x, d = (int)v.y;
            g_src[e] = s; g_dst[e] = d;
            atomicAdd(&g_counts[d], 1);
        }
    } else {
        const int2* p = (const int2*)ei;
        for (int e = tid; e < E; e += nth) {
            int2 v = p[e];
            g_src[e] = v.x; g_dst[e] = v.y;
            atomicAdd(&g_counts[v.y], 1);
        }
    }
    grid_barrier(1);
    if (blockIdx.x == 0 && threadIdx.x == 0) atomicExch(&g_bar[0], 0);

    {
        int gw = tid >> 5;
        int nw = nth >> 5;
        for (int t = gw; t < T; t += nw) {
            int base = t << 8;
            int v[8]; int s = 0;
            #pragma unroll
            for (int j = 0; j < 8; j++) {
                int idx = base + lane * 8 + j;
                int c = (idx < N) ? __ldcg(&g_counts[idx]) : 0;
                v[j] = s; s += c;
            }
            int x = s;
            #pragma unroll
            for (int o = 1; o < 32; o <<= 1) {
                int y = __shfl_up_sync(0xffffffffu, x, o);
                if (lane >= o) x += y;
            }
            int excl = x - s;
            #pragma unroll
            for (int j = 0; j < 8; j++) {
                int idx = base + lane * 8 + j;
                if (idx < N) g_rowptr[idx] = excl + v[j];
            }
            if (lane == 31) g_blocksum[t] = x;
        }
    }
    grid_barrier(2);
    if (blockIdx.x == 0 && threadIdx.x == 0) atomicExch(&g_bar[1], 0);

    if (blockIdx.x == 0 && threadIdx.x < 32) {
        int vals[7]; int s = 0;
        #pragma unroll
        for (int j = 0; j < 7; j++) {
            int idx = lane * 7 + j;
            int v = (idx < T) ? __ldcg(&g_blocksum[idx]) : 0;
            vals[j] = s; s += v;
        }
        int x = s;
        #pragma unroll
        for (int o = 1; o < 32; o <<= 1) {
            int y = __shfl_up_sync(0xffffffffu, x, o);
            if (lane >= o) x += y;
        }
        int excl = x - s;
        #pragma unroll
        for (int j = 0; j < 7; j++) {
            int idx = lane * 7 + j;
            if (idx < T) g_blockoff[idx] = excl + vals[j];
        }
        if (lane == 31) g_rowptr[N] = x;
    }
    grid_barrier(3);
    if (blockIdx.x == 0 && threadIdx.x == 0) atomicExch(&g_bar[2], 0);

    for (int i = tid; i < N; i += nth) {
        int r = __ldcg(&g_rowptr[i]) + __ldcg(&g_blockoff[i >> 8]);
        g_rowptr[i] = r;
        g_cursor[i] = r;
    }
    grid_barrier(4);
    if (blockIdx.x == 0 && threadIdx.x == 0) atomicExch(&g_bar[3], 0);

    for (int e0 = tid * 4; e0 < E; e0 += nth * 4) {
        int d[4], s[4];
        #pragma unroll
        for (int j = 0; j < 4; j++) {
            int e = e0 + j;
            if (e < E) { d[j] = __ldcg(&g_dst[e]); s[j] = __ldcg(&g_src[e]); }
        }
        #pragma unroll
        for (int j = 0; j < 4; j++) {
            int e = e0 + j;
            if (e < E) {
                int p = atomicAdd(&g_cursor[d[j]], 1);
                g_edges[p] = make_int2(s[j], e);
            }
        }
    }
}

// ---------------- fused gather + GEMM: big-grid, 4 nodes/warp ---------------
#define FT 256
#define FW 8                         // warps per block
#define FRPW 4                       // nodes per warp
#define NODES_PER_BLOCK (FW * FRPW)  // 32

__global__ void __launch_bounds__(FT)
k_fused(const float4* __restrict__ X4, const float* __restrict__ eF,
        const float4* __restrict__ W4, const float4* __restrict__ b4p,
        const float4* __restrict__ We4, const float4* __restrict__ be4,
        float4* __restrict__ out4, int N) {
    __shared__ float4 xs[FW][FRPW][32];   // 16 KB

    int tid = threadIdx.x, warp = tid >> 5, lane = tid & 31;
    int row0 = blockIdx.x * NODES_PER_BLOCK + warp * FRPW;

    // ---- gather phase: sum X[src] / edgeFeatures per node (4 nodes/warp)
    float ae[FRPW];
    int   degv[FRPW];
    #pragma unroll
    for (int r = 0; r < FRPW; r++) {
        float4 acc = make_float4(0.f, 0.f, 0.f, 0.f);
        float a = 0.f;
        int deg = 0;
        int row = row0 + r;
        if (row < N) {
            int s0 = __ldcg(&g_rowptr[row]);
            int s1 = __ldcg(&g_rowptr[row + 1]);
            deg = s1 - s0;
            for (int base = s0; base < s1; base += 32) {
                int cnt = s1 - base; if (cnt > 32) cnt = 32;
                int2 se = __ldcg(&g_edges[base + (lane < cnt ? lane : 0)]);
                for (int j = 0; j < cnt; j += 8) {
                    #pragma unroll
                    for (int u = 0; u < 8; u++) {
                        if (j + u < cnt) {  // uniform across warp
                            int sj = __shfl_sync(0xffffffffu, se.x, j + u);
                            int ej = __shfl_sync(0xffffffffu, se.y, j + u);
                            float4 xv = __ldcg(&X4[(long)sj * 32 + lane]);
                            acc.x += xv.x; acc.y += xv.y;
                            acc.z += xv.z; acc.w += xv.w;
                            if (lane < EFD) a += __ldcg(&eF[(long)ej * EFD + lane]);
                        }
                    }
                }
            }
        }
        xs[warp][r][lane] = acc;
        ae[r] = a;
        degv[r] = deg;
    }
    __syncwarp();

    // ---- GEMM phase: 4 rows x 128 cols; W streamed through L1 (__ldg)
    float4 acc[FRPW];
    #pragma unroll
    for (int r = 0; r < FRPW; r++) acc[r] = make_float4(0.f, 0.f, 0.f, 0.f);

    #pragma unroll 2
    for (int k = 0; k < F; k += 4) {
        float4 xv[FRPW];
        #pragma unroll
        for (int r = 0; r < FRPW; r++)
            xv[r] = xs[warp][r][k >> 2];            // smem broadcast
        #pragma unroll
        for (int kk = 0; kk < 4; kk++) {
            float4 w4 = __ldg(&W4[(k + kk) * 32 + lane]);  // L1-resident
            #pragma unroll
            for (int r = 0; r < FRPW; r++) {
                float xk = (kk == 0) ? xv[r].x : (kk == 1) ? xv[r].y
                         : (kk == 2) ? xv[r].z : xv[r].w;
                acc[r].x = fmaf(xk, w4.x, acc[r].x);
                acc[r].y = fmaf(xk, w4.y, acc[r].y);
                acc[r].z = fmaf(xk, w4.z, acc[r].z);
                acc[r].w = fmaf(xk, w4.w, acc[r].w);
            }
        }
    }

    // ---- epilogue: deg*(b+be) + edge GEMM + relu + store
    float4 bb = __ldg(&b4p[lane]);
    float4 be = __ldg(&be4[lane]);
    float4 bs = make_float4(bb.x + be.x, bb.y + be.y, bb.z + be.z, bb.w + be.w);
    #pragma unroll
    for (int r = 0; r < FRPW; r++) {
        int row = row0 + r;
        if (row >= N) break;
        float deg = (float)degv[r];
        float4 o = acc[r];
        o.x = fmaf(deg, bs.x, o.x);
        o.y = fmaf(deg, bs.y, o.y);
        o.z = fmaf(deg, bs.z, o.z);
        o.w = fmaf(deg, bs.w, o.w);
        #pragma unroll
        for (int k = 0; k < EFD; k++) {
            float ek = __shfl_sync(0xffffffffu, ae[r], k);
            float4 w4 = __ldg(&We4[k * 32 + lane]);
            o.x = fmaf(ek, w4.x, o.x);
            o.y = fmaf(ek, w4.y, o.y);
            o.z = fmaf(ek, w4.z, o.z);
            o.w = fmaf(ek, w4.w, o.w);
        }
        o.x = fmaxf(o.x, 0.f); o.y = fmaxf(o.y, 0.f);
        o.z = fmaxf(o.z, 0.f); o.w = fmaxf(o.w, 0.f);
        out4[(long)row * 32 + lane] = o;
    }
}

// ---------------------------------------------------------------------------
extern "C" void kernel_launch(void* const* d_in, const int* in_sizes, int n_in,
                              void* d_out, int out_size) {
    const float* X  = (const float*)d_in[0];
    const void*  EI = d_in[1];
    const float* EF = (const float*)d_in[2];
    const float* W  = (const float*)d_in[3];
    const float* b  = (const float*)d_in[4];
    const float* We = (const float*)d_in[5];
    const float* be = (const float*)d_in[6];
    float* out = (float*)d_out;

    int N = in_sizes[0] / F;
    int E = in_sizes[2] / EFD;

    k_prep<<<PREP_BLOCKS, PREP_T>>>(EI, N, E);
    int nb = (N + NODES_PER_BLOCK - 1) / NODES_PER_BLOCK;
    k_fused<<<nb, FT>>>((const float4*)X, EF, (const float4*)W,
                        (const float4*)b, (const float4*)We,
                        (const float4*)be, (float4*)out, N);
}

// round 6
// speedup vs baseline: 1.3677x; 1.0316x over previous
#include <cuda_runtime.h>
#include <cuda_bf16.h>

#define NMAX 50000
#define EMAX 800000
#define F 128
#define EFD 6

#define PREP_BLOCKS 592
#define PREP_T 512

// ---- packed dual-fp32 ops (Blackwell f32x2) --------------------------------
#define PACK_F32X2(d, a, b) \
    asm("mov.b64 %0, {%1, %2};" : "=l"(d) : "f"(a), "f"(b))
#define FMA_F32X2(d, a, b, c) \
    asm("fma.rn.f32x2 %0, %1, %2, %3;" : "=l"(d) : "l"(a), "l"(b), "l"(c))
#define UNPACK_F32X2(lo, hi, v) \
    asm("mov.b64 {%0, %1}, %2;" : "=f"(lo), "=f"(hi) : "l"(v))

// ---------------- device scratch ----------------
__device__ int    g_is64;
__device__ int    g_counts[NMAX];
__device__ int    g_cursor[NMAX];
__device__ int    g_rowptr[NMAX + 1];
__device__ int    g_src[EMAX];
__device__ int    g_dst[EMAX];
__device__ int2   g_edges[EMAX];
__device__ int    g_blocksum[256];
__device__ int    g_blockoff[256];
__device__ int    g_bar[5];

// ---------------- software grid barrier -------------------------------------
__device__ __forceinline__ void grid_barrier(int id) {
    __syncthreads();
    if (threadIdx.x == 0) {
        __threadfence();
        atomicAdd(&g_bar[id], 1);
        const volatile int* vb = g_bar;
        while (vb[id] < PREP_BLOCKS) { }
        __threadfence();
    }
    __syncthreads();
}

// ---------------- fused prep: zero+detect | hist | scan | scatter ------------
__global__ void __launch_bounds__(PREP_T, 4)
k_prep(const void* __restrict__ ei, int N, int E) {
    const int tid  = blockIdx.x * PREP_T + threadIdx.x;
    const int nth  = PREP_BLOCKS * PREP_T;
    const int lane = threadIdx.x & 31;
    const int T    = (N + 255) >> 8;

    if (blockIdx.x == 0 && threadIdx.x == 0) {
        const long long* p = (const long long*)ei;
        int ok = 1;
        int lim = E < 128 ? E : 128;
        for (int j = 0; j < lim; j++) {
            long long v = p[j];
            if (v < 0 || v >= (long long)N) { ok = 0; break; }
        }
        g_is64 = ok;
        atomicExch(&g_bar[4], 0);
    }
    for (int i = tid; i < N; i += nth) g_counts[i] = 0;
    grid_barrier(0);

    const int is64 = __ldcg(&g_is64);
    if (is64) {
        const longlong2* p = (const longlong2*)ei;
        for (int e = tid; e < E; e += nth) {
            longlong2 v = p[e];
            int s = (int)v.x, d = (int)v.y;
            g_src[e] = s; g_dst[e] = d;
            atomicAdd(&g_counts[d], 1);
        }
    } else {
        const int2* p = (const int2*)ei;
        for (int e = tid; e < E; e += nth) {
            int2 v = p[e];
            g_src[e] = v.x; g_dst[e] = v.y;
            atomicAdd(&g_counts[v.y], 1);
        }
    }
    grid_barrier(1);
    if (blockIdx.x == 0 && threadIdx.x == 0) atomicExch(&g_bar[0], 0);

    {
        int gw = tid >> 5;
        int nw = nth >> 5;
        for (int t = gw; t < T; t += nw) {
            int base = t << 8;
            int v[8]; int s = 0;
            #pragma unroll
            for (int j = 0; j < 8; j++) {
                int idx = base + lane * 8 + j;
                int c = (idx < N) ? __ldcg(&g_counts[idx]) : 0;
                v[j] = s; s += c;
            }
            int x = s;
            #pragma unroll
            for (int o = 1; o < 32; o <<= 1) {
                int y = __shfl_up_sync(0xffffffffu, x, o);
                if (lane >= o) x += y;
            }
            int excl = x - s;
            #pragma unroll
            for (int j = 0; j < 8; j++) {
                int idx = base + lane * 8 + j;
                if (idx < N) g_rowptr[idx] = excl + v[j];
            }
            if (lane == 31) g_blocksum[t] = x;
        }
    }
    grid_barrier(2);
    if (blockIdx.x == 0 && threadIdx.x == 0) atomicExch(&g_bar[1], 0);

    if (blockIdx.x == 0 && threadIdx.x < 32) {
        int vals[7]; int s = 0;
        #pragma unroll
        for (int j = 0; j < 7; j++) {
            int idx = lane * 7 + j;
            int v = (idx < T) ? __ldcg(&g_blocksum[idx]) : 0;
            vals[j] = s; s += v;
        }
        int x = s;
        #pragma unroll
        for (int o = 1; o < 32; o <<= 1) {
            int y = __shfl_up_sync(0xffffffffu, x, o);
            if (lane >= o) x += y;
        }
        int excl = x - s;
        #pragma unroll
        for (int j = 0; j < 7; j++) {
            int idx = lane * 7 + j;
            if (idx < T) g_blockoff[idx] = excl + vals[j];
        }
        if (lane == 31) g_rowptr[N] = x;
    }
    grid_barrier(3);
    if (blockIdx.x == 0 && threadIdx.x == 0) atomicExch(&g_bar[2], 0);

    for (int i = tid; i < N; i += nth) {
        int r = __ldcg(&g_rowptr[i]) + __ldcg(&g_blockoff[i >> 8]);
        g_rowptr[i] = r;
        g_cursor[i] = r;
    }
    grid_barrier(4);
    if (blockIdx.x == 0 && threadIdx.x == 0) atomicExch(&g_bar[3], 0);

    for (int e0 = tid * 4; e0 < E; e0 += nth * 4) {
        int d[4], s[4];
        #pragma unroll
        for (int j = 0; j < 4; j++) {
            int e = e0 + j;
            if (e < E) { d[j] = __ldcg(&g_dst[e]); s[j] = __ldcg(&g_src[e]); }
        }
        #pragma unroll
        for (int j = 0; j < 4; j++) {
            int e = e0 + j;
            if (e < E) {
                int p = atomicAdd(&g_cursor[d[j]], 1);
                g_edges[p] = make_int2(s[j], e);
            }
        }
    }
}

// ---------------- fused gather + GEMM (f32x2), big grid ---------------------
#define FT 256
#define FW 8
#define FRPW 4
#define NODES_PER_BLOCK (FW * FRPW)  // 32

__global__ void __launch_bounds__(FT, 5)
k_fused(const float4* __restrict__ X4, const float* __restrict__ eF,
        const float4* __restrict__ W4, const float4* __restrict__ b4p,
        const float4* __restrict__ We4, const float4* __restrict__ be4,
        float4* __restrict__ out4, int N) {
    __shared__ float4 xs[FW][FRPW][32];   // 16 KB

    int tid = threadIdx.x, warp = tid >> 5, lane = tid & 31;
    int row0 = blockIdx.x * NODES_PER_BLOCK + warp * FRPW;

    // ---- gather phase
    float ae[FRPW];
    int   degv[FRPW];
    #pragma unroll
    for (int r = 0; r < FRPW; r++) {
        float4 acc = make_float4(0.f, 0.f, 0.f, 0.f);
        float a = 0.f;
        int deg = 0;
        int row = row0 + r;
        if (row < N) {
            int s0 = __ldcg(&g_rowptr[row]);
            int s1 = __ldcg(&g_rowptr[row + 1]);
            deg = s1 - s0;
            for (int base = s0; base < s1; base += 32) {
                int cnt = s1 - base; if (cnt > 32) cnt = 32;
                int2 se = __ldcg(&g_edges[base + (lane < cnt ? lane : 0)]);
                for (int j = 0; j < cnt; j += 8) {
                    #pragma unroll
                    for (int u = 0; u < 8; u++) {
                        if (j + u < cnt) {  // uniform across warp
                            int sj = __shfl_sync(0xffffffffu, se.x, j + u);
                            int ej = __shfl_sync(0xffffffffu, se.y, j + u);
                            float4 xv = __ldcg(&X4[(long)sj * 32 + lane]);
                            acc.x += xv.x; acc.y += xv.y;
                            acc.z += xv.z; acc.w += xv.w;
                            if (lane < EFD) a += __ldcg(&eF[(long)ej * EFD + lane]);
                        }
                    }
                }
            }
        }
        xs[warp][r][lane] = acc;
        ae[r] = a;
        degv[r] = deg;
    }
    __syncwarp();

    // ---- GEMM phase: packed f32x2 FMAs, W streamed through L1
    unsigned long long a01[FRPW], a23[FRPW];
    #pragma unroll
    for (int r = 0; r < FRPW; r++) { a01[r] = 0ULL; a23[r] = 0ULL; }

    #pragma unroll 2
    for (int k = 0; k < F; k += 4) {
        float4 xv[FRPW];
        #pragma unroll
        for (int r = 0; r < FRPW; r++)
            xv[r] = xs[warp][r][k >> 2];             // LDS.128 per row
        #pragma unroll
        for (int kk = 0; kk < 4; kk++) {
            float4 w4 = __ldg(&W4[(k + kk) * 32 + lane]);
            unsigned long long w01, w23;
            PACK_F32X2(w01, w4.x, w4.y);             // ALU pipe
            PACK_F32X2(w23, w4.z, w4.w);
            #pragma unroll
            for (int r = 0; r < FRPW; r++) {
                float xk = (kk == 0) ? xv[r].x : (kk == 1) ? xv[r].y
                         : (kk == 2) ? xv[r].z : xv[r].w;
                unsigned long long xk2;
                PACK_F32X2(xk2, xk, xk);
                FMA_F32X2(a01[r], xk2, w01, a01[r]); // FMA pipe, 2 MACs/instr
                FMA_F32X2(a23[r], xk2, w23, a23[r]);
            }
        }
    }

    // ---- epilogue
    float4 bb = __ldg(&b4p[lane]);
    float4 be = __ldg(&be4[lane]);
    float4 bs = make_float4(bb.x + be.x, bb.y + be.y, bb.z + be.z, bb.w + be.w);
    #pragma unroll
    for (int r = 0; r < FRPW; r++) {
        int row = row0 + r;
        if (row >= N) break;
        float deg = (float)degv[r];
        float4 o;
        UNPACK_F32X2(o.x, o.y, a01[r]);
        UNPACK_F32X2(o.z, o.w, a23[r]);
        o.x = fmaf(deg, bs.x, o.x);
        o.y = fmaf(deg, bs.y, o.y);
        o.z = fmaf(deg, bs.z, o.z);
        o.w = fmaf(deg, bs.w, o.w);
        #pragma unroll
        for (int k = 0; k < EFD; k++) {
            float ek = __shfl_sync(0xffffffffu, ae[r], k);
            float4 w4 = __ldg(&We4[k * 32 + lane]);
            o.x = fmaf(ek, w4.x, o.x);
            o.y = fmaf(ek, w4.y, o.y);
            o.z = fmaf(ek, w4.z, o.z);
            o.w = fmaf(ek, w4.w, o.w);
        }
        o.x = fmaxf(o.x, 0.f); o.y = fmaxf(o.y, 0.f);
        o.z = fmaxf(o.z, 0.f); o.w = fmaxf(o.w, 0.f);
        out4[(long)row * 32 + lane] = o;
    }
}

// ---------------------------------------------------------------------------
extern "C" void kernel_launch(void* const* d_in, const int* in_sizes, int n_in,
                              void* d_out, int out_size) {
    const float* X  = (const float*)d_in[0];
    const void*  EI = d_in[1];
    const float* EF = (const float*)d_in[2];
    const float* W  = (const float*)d_in[3];
    const float* b  = (const float*)d_in[4];
    const float* We = (const float*)d_in[5];
    const float* be = (const float*)d_in[6];
    float* out = (float*)d_out;

    int N = in_sizes[0] / F;
    int E = in_sizes[2] / EFD;

    k_prep<<<PREP_BLOCKS, PREP_T>>>(EI, N, E);
    int nb = (N + NODES_PER_BLOCK - 1) / NODES_PER_BLOCK;
    k_fused<<<nb, FT>>>((const float4*)X, EF, (const float4*)W,
                        (const float4*)b, (const float4*)We,
                        (const float4*)be, (float4*)out, N);
}